// round 4
// baseline (speedup 1.0000x reference)
#include <cuda_runtime.h>
#include <math.h>

// Problem constants
#define BB 64
#define NN 8732
#define NN4 (NN / 4)            // 2183
#define CC 21
#define KCAND 200
#define MAXPC 20
#define MAXTOT 20
#define COLBIN 992              // optimistic collect threshold (score >= 0.96875)
#define FULLM 0xffffffffu

#define TILE 128
#define NTILES ((NN + TILE - 1) / TILE)   // 69
#define SLP 129                           // padded smem pitch (bank-conflict free)

// Scratch (static device globals: allowed; no runtime allocation)
__device__ float4 g_boxes[BB * NN];                 // decoded boxes
__device__ float4 g_scoresT4[(size_t)BB * CC * NN4];// masked scores, [b][c][n/4]
__device__ float  g_cls_scores[BB * CC * MAXPC];
__device__ float4 g_cls_boxes[BB * CC * MAXPC];

// ---------------------------------------------------------------------------
// Hybrid bitonic sort of 512 u64 keys, descending. 256 threads; thread t owns
// elements 2t, 2t+1 in registers. j<=32 stages via registers/shfl (no
// barriers); j in {64,128,256} via smem (2 barriers each -> 12 total).
// Caller: __syncthreads() before (sk filled) and after (sk written back).
// ---------------------------------------------------------------------------
__device__ __forceinline__ void sort512_desc(unsigned long long* sk, int t) {
    unsigned long long a = sk[2 * t], b = sk[2 * t + 1];
#pragma unroll
    for (int k = 2; k <= 512; k <<= 1) {
#pragma unroll
        for (int j = k >> 1; j >= 1; j >>= 1) {
            const bool desc = (((2 * t) & k) == 0);
            if (j == 1) {
                unsigned long long hi = a > b ? a : b;
                unsigned long long lo = a > b ? b : a;
                a = desc ? hi : lo;
                b = desc ? lo : hi;
            } else if (j <= 32) {
                const int  l     = j >> 1;
                const bool lower = ((t & l) == 0);
                const bool wmax  = (desc == lower);
                unsigned long long oa = __shfl_xor_sync(FULLM, a, l);
                unsigned long long ob = __shfl_xor_sync(FULLM, b, l);
                a = wmax ? (a > oa ? a : oa) : (a < oa ? a : oa);
                b = wmax ? (b > ob ? b : ob) : (b < ob ? b : ob);
            } else {
                __syncthreads();
                sk[2 * t]     = a;
                sk[2 * t + 1] = b;
                __syncthreads();
                unsigned long long oa = sk[(2 * t) ^ j];
                unsigned long long ob = sk[(2 * t + 1) ^ j];
                const bool lower = (((2 * t) & j) == 0);
                const bool wmax  = (desc == lower);
                a = wmax ? (a > oa ? a : oa) : (a < oa ? a : oa);
                b = wmax ? (b > ob ? b : ob) : (b < ob ? b : ob);
            }
        }
    }
    sk[2 * t]     = a;
    sk[2 * t + 1] = b;
}

// ---------------------------------------------------------------------------
// Kernel A: decode boxes + argmax mask + transposed masked-score write.
// Block = 128 threads handles 128 anchors of one batch (full parallelism).
// ---------------------------------------------------------------------------
__global__ __launch_bounds__(TILE) void decode_kernel(
        const float* __restrict__ deltas,
        const float* __restrict__ labels,
        const float* __restrict__ anchors) {
    const int b    = blockIdx.x / NTILES;
    const int tile = blockIdx.x % NTILES;
    const int n0   = tile * TILE;
    const int cnt  = min(TILE, NN - n0);        // 128 or 28; always mult of 4
    const int t    = threadIdx.x;

    __shared__ float         sl[CC * SLP];      // [class][anchor], padded
    __shared__ unsigned char sm[TILE];

    // Coalesced global read, class-major smem write (pitch 129 avoids conflicts)
    const float* Lb  = labels + ((size_t)b * NN + n0) * CC;
    const int    tot = cnt * CC;
    for (int idx = t; idx < tot; idx += TILE) {
        int i = idx / CC;
        int c = idx - i * CC;
        sl[c * SLP + i] = Lb[idx];
    }
    __syncthreads();

    if (t < cnt) {
        // argmax over 21 classes (first-occurrence ties, like jnp.argmax)
        float best = sl[t];
        int   bi   = 0;
#pragma unroll
        for (int c = 1; c < CC; c++) {
            float v = sl[c * SLP + t];
            if (v > best) { best = v; bi = c; }
        }
        sm[t] = (bi != 0) ? 1 : 0;

        // decode box
        const int n = n0 + t;
        float4 a = __ldg(((const float4*)anchors) + n);
        float4 d = __ldg(((const float4*)deltas) + (size_t)b * NN + n);
        d.x *= 0.1f; d.y *= 0.1f; d.z *= 0.2f; d.w *= 0.2f;

        float ah  = a.z - a.x;
        float aw  = a.w - a.y;
        float acy = a.x + 0.5f * ah;
        float acx = a.y + 0.5f * aw;
        float cy  = d.x * ah + acy;
        float cx  = d.y * aw + acx;
        float h   = expf(d.z) * ah;
        float w   = expf(d.w) * aw;

        g_boxes[(size_t)b * NN + n] = make_float4(cy - 0.5f * h, cx - 0.5f * w,
                                                  cy + 0.5f * h, cx + 0.5f * w);
    }
    __syncthreads();

    // Transposed masked-score write, float4 per (class, anchor-quad)
    const int g4 = cnt >> 2;                    // quads per class (32 or 7)
    for (int idx = t; idx < CC * g4; idx += TILE) {
        const int c  = idx / g4;
        const int i4 = idx - c * g4;
        float4 v;
        const int ib = i4 * 4;
        v.x = sm[ib + 0] ? sl[c * SLP + ib + 0] : 0.0f;
        v.y = sm[ib + 1] ? sl[c * SLP + ib + 1] : 0.0f;
        v.z = sm[ib + 2] ? sl[c * SLP + ib + 2] : 0.0f;
        v.w = sm[ib + 3] ? sl[c * SLP + ib + 3] : 0.0f;
        g_scoresT4[((size_t)b * CC + c) * NN4 + (n0 >> 2) + i4] = v;
    }
}

// ---------------------------------------------------------------------------
// IoU, exactly mirroring the reference fp32 formula
// ---------------------------------------------------------------------------
__device__ __forceinline__ float iou_f(float4 A, float4 B2) {
    float areaA = (A.z - A.x) * (A.w - A.y);
    float areaB = (B2.z - B2.x) * (B2.w - B2.y);
    float ih = fminf(A.z, B2.z) - fmaxf(A.x, B2.x); ih = fmaxf(ih, 0.0f);
    float iw = fminf(A.w, B2.w) - fmaxf(A.y, B2.y); iw = fmaxf(iw, 0.0f);
    float inter = ih * iw;
    return inter / (areaA + areaB - inter + 1e-8f);
}

// ---------------------------------------------------------------------------
// Kernel B: per-(b,c) exact top-200 select + greedy NMS (single warp) +
// first-20 output. One block (256 threads) per (b,c). 1344 blocks.
// ---------------------------------------------------------------------------
__global__ __launch_bounds__(256) void nms_kernel() {
    const int b = blockIdx.x / CC;
    const int c = blockIdx.x % CC;
    const int t = threadIdx.x;

    __shared__ int                hist[1024];
    __shared__ unsigned long long sk[512];
    __shared__ float4             sbox[KCAND];
    __shared__ float              sscore[KCAND];
    __shared__ int                s_count, s_cut;

    for (int i = t; i < 1024; i += 256) hist[i] = 0;
    if (t == 0) s_count = 0;
    __syncthreads();

    const float4* S4 = g_scoresT4 + ((size_t)b * CC + c) * NN4;

    // Pass 1: histogram + optimistic collect (bin >= COLBIN)
    for (int i = t; i < NN4; i += 256) {
        float4 v = __ldg(S4 + i);
        float ss[4] = { v.x, v.y, v.z, v.w };
#pragma unroll
        for (int k = 0; k < 4; k++) {
            float s = ss[k];
            if (s > 0.0f) {
                int bin = min((int)(s * 1024.0f), 1023);
                atomicAdd(&hist[bin], 1);
                if (bin >= COLBIN) {
                    int p = atomicAdd(&s_count, 1);
                    if (p < 512) {
                        unsigned n = (unsigned)(i * 4 + k);
                        sk[p] = ((unsigned long long)__float_as_uint(s) << 32)
                                | (unsigned)(~n);
                    }
                }
            }
        }
    }
    __syncthreads();

    // Warp-parallel top-200 cutoff: suffix-scan over 32 super-bins, then a
    // short serial drill within the crossing super-bin.
    if (t < 32) {
        int s = 0;
#pragma unroll
        for (int q = 0; q < 32; q++) s += hist[t * 32 + q];
        int S = s;
#pragma unroll
        for (int o = 1; o < 32; o <<= 1) {
            int v = __shfl_down_sync(FULLM, S, o);
            if (t + o < 32) S += v;
        }
        unsigned bal = __ballot_sync(FULLM, S >= KCAND);
        int ls = bal ? (31 - __clz(bal)) : -1;
        int Snext = __shfl_sync(FULLM, S, (ls >= 0 && ls < 31) ? ls + 1 : 31);
        if (t == 0) {
            int cut = 0;
            if (ls >= 0) {
                int cum = (ls < 31) ? Snext : 0;
                for (int bin = ls * 32 + 31; bin >= ls * 32; bin--) {
                    cum += hist[bin];
                    if (cum >= KCAND) { cut = bin; break; }
                }
            }
            s_cut = cut;
        }
    }
    __syncthreads();
    const int cut = s_cut;

    // Exact fallback: re-read row (L2 resident) if optimistic set insufficient
    if (cut < COLBIN || s_count > 512) {
        __syncthreads();
        if (t == 0) s_count = 0;
        __syncthreads();
        for (int i = t; i < NN4; i += 256) {
            float4 v = __ldg(S4 + i);
            float ss[4] = { v.x, v.y, v.z, v.w };
#pragma unroll
            for (int k = 0; k < 4; k++) {
                float s = ss[k];
                if (s > 0.0f) {
                    int bin = min((int)(s * 1024.0f), 1023);
                    if (bin >= cut) {
                        int p = atomicAdd(&s_count, 1);
                        if (p < 512) {
                            unsigned n = (unsigned)(i * 4 + k);
                            sk[p] = ((unsigned long long)__float_as_uint(s) << 32)
                                    | (unsigned)(~n);
                        }
                    }
                }
            }
        }
    }
    __syncthreads();
    const int M = min(s_count, 512);
    for (int i = M + t; i < 512; i += 256) sk[i] = 0ULL;
    __syncthreads();

    sort512_desc(sk, t);
    __syncthreads();

    // Expand top-200 into score/box smem
    if (t < KCAND) {
        unsigned long long kk = sk[t];
        float s = __uint_as_float((unsigned)(kk >> 32));
        sscore[t] = s;
        float4 bx = make_float4(0.f, 0.f, 0.f, 0.f);
        if (s > 0.0f) bx = g_boxes[(size_t)b * NN + (~(unsigned)kk)];
        sbox[t] = bx;
    }
    __syncthreads();

    // Single-warp greedy NMS: candidate idx -> (lane = idx&31, slot = idx>>5),
    // suppression masks in registers, no block barriers.
    if (t < 32) {
        const int lane = t;
        const int outbase = (b * CC + c) * MAXPC;
        float4 mybox[7];
#pragma unroll
        for (int m = 0; m < 7; m++) {
            int idx = lane + 32 * m;
            mybox[m] = (idx < KCAND) ? sbox[idx]
                                     : make_float4(0.f, 0.f, 0.f, 0.f);
        }
        unsigned sup = 0;
        int kc = 0;
        for (int i = 0; i < KCAND; i++) {
            float si = sscore[i];
            if (si <= 0.5f) break;                       // sorted: all later <=
            unsigned om = __shfl_sync(FULLM, sup, i & 31);
            if (!((om >> (i >> 5)) & 1)) {
                if (lane == 0) {
                    g_cls_scores[outbase + kc] = si;
                    g_cls_boxes[outbase + kc]  = sbox[i];
                }
                kc++;
                if (kc >= MAXPC) break;                  // first-20 complete
                float4 bi = sbox[i];
#pragma unroll
                for (int m = 0; m < 7; m++) {
                    int idx = lane + 32 * m;
                    if (idx > i && idx < KCAND && !((sup >> m) & 1)) {
                        if (iou_f(bi, mybox[m]) > 0.5f) sup |= (1u << m);
                    }
                }
            }
        }
        if (lane < MAXPC && lane >= kc) {
            g_cls_scores[outbase + lane] = 0.0f;
            g_cls_boxes[outbase + lane]  = make_float4(0.f, 0.f, 0.f, 0.f);
        }
    }
}

// ---------------------------------------------------------------------------
// Kernel C: per-batch merge of 21*20 = 420 entries -> top-20 overall
// ---------------------------------------------------------------------------
__global__ __launch_bounds__(256) void merge_kernel(float* __restrict__ out) {
    const int b = blockIdx.x;
    const int t = threadIdx.x;
    __shared__ unsigned long long sk[512];

    for (int i = t; i < 512; i += 256) {
        unsigned long long kk = 0ULL;
        if (i < CC * MAXPC) {
            float s = g_cls_scores[b * CC * MAXPC + i];
            kk = ((unsigned long long)__float_as_uint(s) << 32)
                 | (unsigned)(~(unsigned)i);
        }
        sk[i] = kk;
    }
    __syncthreads();

    sort512_desc(sk, t);
    __syncthreads();

    if (t < MAXTOT) {
        unsigned long long kk = sk[t];
        float s   = __uint_as_float((unsigned)(kk >> 32));
        float4 bx = make_float4(0.f, 0.f, 0.f, 0.f);
        float lab = 0.0f;
        if (s > 0.0f) {
            unsigned fi = ~(unsigned)kk;   // flat index in [0, 420)
            bx = g_cls_boxes[b * CC * MAXPC + fi];
            bx.x = fminf(fmaxf(bx.x, 0.0f), 1.0f);
            bx.y = fminf(fmaxf(bx.y, 0.0f), 1.0f);
            bx.z = fminf(fmaxf(bx.z, 0.0f), 1.0f);
            bx.w = fminf(fmaxf(bx.w, 0.0f), 1.0f);
            lab = (float)(fi / MAXPC);
        }
        // Output layout: boxes [B,20,4] | vals [B,20] | labels [B,20]
        float* ob = out + (size_t)b * MAXTOT * 4;
        float* ov = out + (size_t)BB * MAXTOT * 4 + (size_t)b * MAXTOT;
        float* ol = out + (size_t)BB * MAXTOT * 4 + (size_t)BB * MAXTOT
                        + (size_t)b * MAXTOT;
        ob[t * 4 + 0] = bx.x;
        ob[t * 4 + 1] = bx.y;
        ob[t * 4 + 2] = bx.z;
        ob[t * 4 + 3] = bx.w;
        ov[t] = s;
        ol[t] = lab;
    }
}

// ---------------------------------------------------------------------------
extern "C" void kernel_launch(void* const* d_in, const int* in_sizes, int n_in,
                              void* d_out, int out_size) {
    const float* deltas  = (const float*)d_in[0];  // (64, 8732, 4)
    const float* labels  = (const float*)d_in[1];  // (64, 8732, 21)
    const float* anchors = (const float*)d_in[2];  // (8732, 4)
    float* out = (float*)d_out;

    decode_kernel<<<BB * NTILES, TILE>>>(deltas, labels, anchors);
    nms_kernel<<<BB * CC, 256>>>();
    merge_kernel<<<BB, 256>>>(out);
}